// round 7
// baseline (speedup 1.0000x reference)
#include <cuda_runtime.h>
#include <cuda_bf16.h>

// Problem constants
#define PN   64
#define PTC  256
#define PK   32
#define PTK  64
#define PD   256
#define D4   (PD/4)          // 64 float4 per row
#define FULL_T (PTK + PTC)   // 320

#define NB_KNOW (PN * PK)                  // 2048
#define NB_POOL (NB_KNOW + PN)             // 2112
#define NB_GCTX ((PN * PTC) / 4)           // 4096 (4 ctx rows per block)
#define NB_MEGA (NB_POOL + NB_GCTX)        // 6208

// Scratch (device globals — no allocation allowed). Zero-initialized at load;
// g_cnt is reset to 0 by its last user every launch => replay-deterministic.
__device__ float g_ctx_use[PN * PD];
__device__ float g_know_use[PN * PK * PD];
__device__ int   g_cnt[PN];

// ck_mask dtype probe: jax bool may arrive as 1-byte bool or int32.
__device__ __forceinline__ bool ck_mask_at(const unsigned char* p, int idx) {
    unsigned int w0 = *(const unsigned int*)p;
    if ((w0 & 0xFFFFFF00u) != 0u) {
        return p[idx] != 0;                          // int8 bool layout
    } else {
        return ((const int*)p)[idx] != 0;            // int32 layout
    }
}

// 8-wide batched accumulate: 8 independent LDG.128.CG in flight, then FMAs.
__device__ __forceinline__ void batch8(const float4* __restrict__ e4,
                                       const int* __restrict__ toks,
                                       int t0, int j,
                                       float4& acc, float& lenf)
{
    int tk[8];
    #pragma unroll
    for (int i = 0; i < 8; i++) tk[i] = toks[t0 + i];
    float4 v[8];
    #pragma unroll
    for (int i = 0; i < 8; i++) v[i] = __ldcg(&e4[(size_t)tk[i] * D4 + j]);
    #pragma unroll
    for (int i = 0; i < 8; i++) {
        float w = (tk[i] != 0) ? 1.0f : 0.0f;
        acc.x = fmaf(w, v[i].x, acc.x);
        acc.y = fmaf(w, v[i].y, acc.y);
        acc.z = fmaf(w, v[i].z, acc.z);
        acc.w = fmaf(w, v[i].w, acc.w);
        lenf += w;
    }
}

// ---------------------------------------------------------------------------
// ONE kernel, three block roles:
//   b in [0, 2048):        know pooling (n = b/32)
//   b in [2048, 2112):     ctx pooling (n = b-2048)
//   b in [2112, 6208):     gather_ctx (no dependencies)
// The 33rd pool block to finish for a batch n (per-n atomic counter) inlines
// the attention scoring + argmax + ck_attn write + selected-knowledge gather,
// eliminating the two tail kernel launches.
// ---------------------------------------------------------------------------
__global__ __launch_bounds__(256, 4)
void mega_kernel(const int* __restrict__ src_tokens,
                 const int* __restrict__ know_tokens,
                 const unsigned char* __restrict__ ckm,
                 const int* __restrict__ cs_ids,
                 const int* __restrict__ use_cs_ids,
                 const float* __restrict__ embed,
                 float* __restrict__ out_enc,
                 float* __restrict__ out_mask,
                 float* __restrict__ out_ck_attn)
{
    __shared__ int    toks[PTC];
    __shared__ float4 part[4][D4];     // 4 KB
    __shared__ float  lenp[4];
    __shared__ float  scores[PK];
    __shared__ int    is_last, cs_sh;

    const int tid = threadIdx.x;
    const int j   = tid & 63;
    const int tq  = tid >> 6;
    const int b   = blockIdx.x;
    const float4* __restrict__ e4 = (const float4*)embed;

    if (b >= NB_POOL) {
        // ---- gather_ctx: 4 output rows per block, branchless ----
        const int rc = (b - NB_POOL) * 4 + tq;      // 0 .. N*TC-1
        const int n  = rc >> 8;                      // / 256
        const int tc = rc & 255;
        const int tok = src_tokens[n * PTC + tc];
        const float w = (tok != 0) ? 1.0f : 0.0f;
        const int row = (tok != 0) ? tok : 0;
        float4 v = __ldcg(&e4[(size_t)row * D4 + j]);
        const size_t r = (size_t)n * FULL_T + PTK + tc;
        __stcs(&((float4*)out_enc)[r * D4 + j],
               make_float4(w * v.x, w * v.y, w * v.z, w * v.w));
        if (j == 0) out_mask[r] = w;
        return;
    }

    // ---------------- pooling ----------------
    float4 acc = make_float4(0.f, 0.f, 0.f, 0.f);
    float  lenf = 0.f;
    float* dst;
    int n;

    if (b < NB_KNOW) {
        n = b / PK;
        if (tid < PTK) toks[tid] = know_tokens[(size_t)b * PTK + tid];
        __syncthreads();
        const float cmv = ck_mask_at(ckm, n * PK + (b % PK)) ? 1.0f : 0.0f;

        const int t0 = tq * 16;
        batch8(e4, toks, t0,     j, acc, lenf);
        batch8(e4, toks, t0 + 8, j, acc, lenf);

        acc.x *= cmv; acc.y *= cmv; acc.z *= cmv; acc.w *= cmv;
        lenf *= cmv;
        dst = g_know_use + (size_t)b * PD;
    } else {
        n = b - NB_KNOW;
        toks[tid] = src_tokens[n * PTC + tid];
        __syncthreads();

        const int t0 = tq * 64;
        #pragma unroll
        for (int bt = 0; bt < 8; bt++)
            batch8(e4, toks, t0 + bt * 8, j, acc, lenf);

        dst = g_ctx_use + (size_t)n * PD;
    }

    part[tq][j] = acc;
    if (j == 0) lenp[tq] = lenf;
    __syncthreads();

    if (tq == 0) {
        float4 p0 = part[0][j], p1 = part[1][j], p2 = part[2][j], p3 = part[3][j];
        float4 a = make_float4(p0.x + p1.x + p2.x + p3.x,
                               p0.y + p1.y + p2.y + p3.y,
                               p0.z + p1.z + p2.z + p3.z,
                               p0.w + p1.w + p2.w + p3.w);
        float L = lenp[0] + lenp[1] + lenp[2] + lenp[3];
        float s = rsqrtf(256.0f * fmaxf(L, 1.0f));
        ((float4*)dst)[j] = make_float4(a.x * s, a.y * s, a.z * s, a.w * s);
        __threadfence();                    // publish before counter bump
    }
    __syncthreads();

    if (tid == 0) {
        int old = atomicAdd(&g_cnt[n], 1);
        is_last = (old == 32);              // 33rd arrival owns the tail
        if (old == 32) atomicExch(&g_cnt[n], 0);   // reset for next replay
    }
    __syncthreads();
    if (!is_last) return;

    // ---------------- tail: attn scores + argmax for this n ----------------
    {
        const int wid  = tid >> 5;
        const int lane = tid & 31;
        const float* __restrict__ cu = g_ctx_use + (size_t)n * PD;
        float cureg[8];
        #pragma unroll
        for (int c = 0; c < 8; c++) cureg[c] = __ldcg(cu + lane + 32 * c);

        for (int k = wid; k < PK; k += 8) {
            const float* __restrict__ ku = g_know_use + ((size_t)n * PK + k) * PD;
            float p = 0.f;
            #pragma unroll
            for (int c = 0; c < 8; c++) p = fmaf(__ldcg(ku + lane + 32 * c), cureg[c], p);
            #pragma unroll
            for (int o = 16; o; o >>= 1) p += __shfl_xor_sync(0xFFFFFFFFu, p, o);
            if (lane == 0) scores[k] = p;
        }
    }
    __syncthreads();

    if (tid == 0) {
        int use = *use_cs_ids;
        int best = 0;
        float bv = -__int_as_float(0x7f800000);  // -inf
        #pragma unroll
        for (int k = 0; k < PK; k++) {
            float v = ck_mask_at(ckm, n * PK + k) ? scores[k] : -__int_as_float(0x7f800000);
            if (v > bv) { bv = v; best = k; }   // first-max matches jnp.argmax
        }
        cs_sh = use ? cs_ids[n] : best;
    }
    if (tid < PK) {
        bool cm = ck_mask_at(ckm, n * PK + tid);
        out_ck_attn[n * PK + tid] = cm ? scores[tid] : 0.0f;
    }
    __syncthreads();

    // ---------------- tail: gather selected knowledge rows ----------------
    const int cs = cs_sh;
    if (tid < PTK) toks[tid] = know_tokens[((size_t)n * PK + cs) * PTK + tid];
    __syncthreads();
    const bool cmn = ck_mask_at(ckm, n * PK + cs);

    #pragma unroll
    for (int t = tq; t < PTK; t += 4) {
        const int tok = toks[t];
        const bool m = cmn && (tok != 0);
        const float w = m ? 1.0f : 0.0f;
        const int row = m ? tok : 0;
        float4 v = __ldcg(&e4[(size_t)row * D4 + j]);
        const size_t r = (size_t)n * FULL_T + t;
        __stcs(&((float4*)out_enc)[r * D4 + j],
               make_float4(w * v.x, w * v.y, w * v.z, w * v.w));
    }
    if (tid < PTK) {
        const int tok = toks[tid];
        out_mask[(size_t)n * FULL_T + tid] = (cmn && tok != 0) ? 1.0f : 0.0f;
    }
}

// ---------------------------------------------------------------------------
extern "C" void kernel_launch(void* const* d_in, const int* in_sizes, int n_in,
                              void* d_out, int out_size)
{
    const int*           src_tokens  = (const int*)d_in[0];            // [N,TC]
    const int*           know_tokens = (const int*)d_in[1];            // [N,K,TK]
    const unsigned char* ck_mask     = (const unsigned char*)d_in[2];  // [N,K] bool
    const int*           cs_ids      = (const int*)d_in[3];            // [N]
    const int*           use_cs_ids  = (const int*)d_in[4];            // scalar
    const float*         embed       = (const float*)d_in[5];          // [V,D]

    float* out = (float*)d_out;
    float* out_enc     = out;                                   // N*320*256
    float* out_mask    = out + (size_t)PN * FULL_T * PD;        // N*320
    float* out_ck_attn = out_mask + (size_t)PN * FULL_T;        // N*K

    mega_kernel<<<NB_MEGA, 256>>>(src_tokens, know_tokens, ck_mask,
                                  cs_ids, use_cs_ids, embed,
                                  out_enc, out_mask, out_ck_attn);
}

// round 8
// speedup vs baseline: 1.1566x; 1.1566x over previous
#include <cuda_runtime.h>
#include <cuda_bf16.h>

// Problem constants
#define PN   64
#define PTC  256
#define PK   32
#define PTK  64
#define PD   256
#define D4   (PD/4)          // 64 float4 per row
#define FULL_T (PTK + PTC)   // 320

#define NB_KNOW (PN * PK)                  // 2048
#define NB_POOL (NB_KNOW + PN)             // 2112
#define NB_GCTX ((PN * PTC) / 4)           // 4096 (4 ctx rows per block)
#define NB_MEGA (NB_POOL + NB_GCTX)        // 6208

// Scratch (device globals — no allocation allowed)
__device__ float g_ctx_use[PN * PD];
__device__ float g_know_use[PN * PK * PD];

// ck_mask dtype probe: jax bool may arrive as 1-byte bool or int32.
__device__ __forceinline__ bool ck_mask_at(const unsigned char* p, int idx) {
    unsigned int w0 = *(const unsigned int*)p;
    if ((w0 & 0xFFFFFF00u) != 0u) {
        return p[idx] != 0;                          // int8 bool layout
    } else {
        return ((const int*)p)[idx] != 0;            // int32 layout
    }
}

// 8-wide batched accumulate: 8 independent LDG.128.CG in flight, then FMAs.
__device__ __forceinline__ void batch8(const float4* __restrict__ e4,
                                       const int* __restrict__ toks,
                                       int t0, int j,
                                       float4& acc, float& lenf)
{
    int tk[8];
    #pragma unroll
    for (int i = 0; i < 8; i++) tk[i] = toks[t0 + i];
    float4 v[8];
    #pragma unroll
    for (int i = 0; i < 8; i++) v[i] = __ldcg(&e4[(size_t)tk[i] * D4 + j]);
    #pragma unroll
    for (int i = 0; i < 8; i++) {
        float w = (tk[i] != 0) ? 1.0f : 0.0f;
        acc.x = fmaf(w, v[i].x, acc.x);
        acc.y = fmaf(w, v[i].y, acc.y);
        acc.z = fmaf(w, v[i].z, acc.z);
        acc.w = fmaf(w, v[i].w, acc.w);
        lenf += w;
    }
}

// ---------------------------------------------------------------------------
// Mega kernel (clean R6 version — no fences/atomics on the hot path):
//   b in [0, 2048):        know pooling (n = b/32)
//   b in [2048, 2112):     ctx pooling (n = b-2048)
//   b in [2112, 6208):     gather_ctx (no dependencies)
// ---------------------------------------------------------------------------
__global__ __launch_bounds__(256, 4)
void mega_kernel(const int* __restrict__ src_tokens,
                 const int* __restrict__ know_tokens,
                 const unsigned char* __restrict__ ckm,
                 const float* __restrict__ embed,
                 float* __restrict__ out_enc,
                 float* __restrict__ out_mask)
{
    __shared__ int    toks[PTC];
    __shared__ float4 part[4][D4];     // 4 KB
    __shared__ float  lenp[4];

    const int tid = threadIdx.x;
    const int j   = tid & 63;
    const int tq  = tid >> 6;
    const int b   = blockIdx.x;
    const float4* __restrict__ e4 = (const float4*)embed;

    if (b >= NB_POOL) {
        // ---- gather_ctx: 4 output rows per block, branchless ----
        const int rc = (b - NB_POOL) * 4 + tq;      // 0 .. N*TC-1
        const int n  = rc >> 8;                      // / 256
        const int tc = rc & 255;
        const int tok = src_tokens[n * PTC + tc];
        const float w = (tok != 0) ? 1.0f : 0.0f;
        const int row = (tok != 0) ? tok : 0;
        float4 v = __ldcg(&e4[(size_t)row * D4 + j]);
        const size_t r = (size_t)n * FULL_T + PTK + tc;
        __stcs(&((float4*)out_enc)[r * D4 + j],
               make_float4(w * v.x, w * v.y, w * v.z, w * v.w));
        if (j == 0) out_mask[r] = w;
        return;
    }

    float4 acc = make_float4(0.f, 0.f, 0.f, 0.f);
    float  lenf = 0.f;
    float* dst;

    if (b < NB_KNOW) {
        const int n = b / PK;
        if (tid < PTK) toks[tid] = know_tokens[(size_t)b * PTK + tid];
        __syncthreads();
        const float cmv = ck_mask_at(ckm, n * PK + (b % PK)) ? 1.0f : 0.0f;

        const int t0 = tq * 16;
        batch8(e4, toks, t0,     j, acc, lenf);
        batch8(e4, toks, t0 + 8, j, acc, lenf);

        acc.x *= cmv; acc.y *= cmv; acc.z *= cmv; acc.w *= cmv;
        lenf *= cmv;
        dst = g_know_use + (size_t)b * PD;
    } else {
        const int n = b - NB_KNOW;
        toks[tid] = src_tokens[n * PTC + tid];
        __syncthreads();

        const int t0 = tq * 64;
        #pragma unroll
        for (int bt = 0; bt < 8; bt++)
            batch8(e4, toks, t0 + bt * 8, j, acc, lenf);

        dst = g_ctx_use + (size_t)n * PD;
    }

    part[tq][j] = acc;
    if (j == 0) lenp[tq] = lenf;
    __syncthreads();

    if (tq == 0) {
        float4 p0 = part[0][j], p1 = part[1][j], p2 = part[2][j], p3 = part[3][j];
        float4 a = make_float4(p0.x + p1.x + p2.x + p3.x,
                               p0.y + p1.y + p2.y + p3.y,
                               p0.z + p1.z + p2.z + p3.z,
                               p0.w + p1.w + p2.w + p3.w);
        float L = lenp[0] + lenp[1] + lenp[2] + lenp[3];
        float s = rsqrtf(256.0f * fmaxf(L, 1.0f));
        ((float4*)dst)[j] = make_float4(a.x * s, a.y * s, a.z * s, a.w * s);
    }
}

// ---------------------------------------------------------------------------
// Fused tail: one block per n (64 blocks, 256 threads).
//   Phase A: 32 attn scores + argmax + ck_attn write.
//   Phase B: gather the 64 selected knowledge rows (4-deep load batching).
// ---------------------------------------------------------------------------
__global__ __launch_bounds__(256)
void tail_kernel(const int* __restrict__ know_tokens,
                 const unsigned char* __restrict__ ckm,
                 const int* __restrict__ cs_ids,
                 const int* __restrict__ use_cs_ids,
                 const float* __restrict__ embed,
                 float* __restrict__ out_enc,
                 float* __restrict__ out_mask,
                 float* __restrict__ out_ck_attn)
{
    const int n    = blockIdx.x;
    const int tid  = threadIdx.x;
    const int wid  = tid >> 5;
    const int lane = tid & 31;
    const int j    = tid & 63;
    const int tq   = tid >> 6;
    __shared__ float scores[PK];
    __shared__ int   toks[PTK];
    __shared__ int   cs_sh;

    // ---- Phase A: scores ----
    const float* __restrict__ cu = g_ctx_use + (size_t)n * PD;
    float cureg[8];
    #pragma unroll
    for (int c = 0; c < 8; c++) cureg[c] = cu[lane + 32 * c];

    #pragma unroll
    for (int kk = 0; kk < 4; kk++) {
        const int k = wid + kk * 8;
        const float* __restrict__ ku = g_know_use + ((size_t)n * PK + k) * PD;
        float p = 0.f;
        #pragma unroll
        for (int c = 0; c < 8; c++) p = fmaf(ku[lane + 32 * c], cureg[c], p);
        #pragma unroll
        for (int o = 16; o; o >>= 1) p += __shfl_xor_sync(0xFFFFFFFFu, p, o);
        if (lane == 0) scores[k] = p;
    }
    __syncthreads();

    if (tid == 0) {
        int use = *use_cs_ids;
        int best = 0;
        float bv = -__int_as_float(0x7f800000);  // -inf
        #pragma unroll
        for (int k = 0; k < PK; k++) {
            float v = ck_mask_at(ckm, n * PK + k) ? scores[k] : -__int_as_float(0x7f800000);
            if (v > bv) { bv = v; best = k; }   // first-max matches jnp.argmax
        }
        cs_sh = use ? cs_ids[n] : best;
    }
    if (tid < PK) {
        bool cm = ck_mask_at(ckm, n * PK + tid);
        out_ck_attn[n * PK + tid] = cm ? scores[tid] : 0.0f;
    }
    __syncthreads();

    // ---- Phase B: gather selected knowledge rows ----
    const int cs = cs_sh;
    if (tid < PTK) toks[tid] = know_tokens[((size_t)n * PK + cs) * PTK + tid];
    __syncthreads();
    const bool cmn = ck_mask_at(ckm, n * PK + cs);
    const float4* __restrict__ e4 = (const float4*)embed;

    // 16 rows per tq-group, processed 4 at a time for MLP.
    #pragma unroll
    for (int g = 0; g < 4; g++) {
        int   rows[4];
        float ws[4];
        float4 v[4];
        #pragma unroll
        for (int i = 0; i < 4; i++) {
            const int t = tq + 4 * (g * 4 + i);
            const int tok = toks[t];
            const bool m = cmn && (tok != 0);
            ws[i]   = m ? 1.0f : 0.0f;
            rows[i] = m ? tok : 0;
        }
        #pragma unroll
        for (int i = 0; i < 4; i++) v[i] = __ldcg(&e4[(size_t)rows[i] * D4 + j]);
        #pragma unroll
        for (int i = 0; i < 4; i++) {
            const int t = tq + 4 * (g * 4 + i);
            const size_t r = (size_t)n * FULL_T + t;
            __stcs(&((float4*)out_enc)[r * D4 + j],
                   make_float4(ws[i] * v[i].x, ws[i] * v[i].y,
                               ws[i] * v[i].z, ws[i] * v[i].w));
        }
    }
    if (tid < PTK) {
        const int tok = toks[tid];
        out_mask[(size_t)n * FULL_T + tid] = (cmn && tok != 0) ? 1.0f : 0.0f;
    }
}

// ---------------------------------------------------------------------------
extern "C" void kernel_launch(void* const* d_in, const int* in_sizes, int n_in,
                              void* d_out, int out_size)
{
    const int*           src_tokens  = (const int*)d_in[0];            // [N,TC]
    const int*           know_tokens = (const int*)d_in[1];            // [N,K,TK]
    const unsigned char* ck_mask     = (const unsigned char*)d_in[2];  // [N,K] bool
    const int*           cs_ids      = (const int*)d_in[3];            // [N]
    const int*           use_cs_ids  = (const int*)d_in[4];            // scalar
    const float*         embed       = (const float*)d_in[5];          // [V,D]

    float* out = (float*)d_out;
    float* out_enc     = out;                                   // N*320*256
    float* out_mask    = out + (size_t)PN * FULL_T * PD;        // N*320
    float* out_ck_attn = out_mask + (size_t)PN * FULL_T;        // N*K

    mega_kernel<<<NB_MEGA, 256>>>(src_tokens, know_tokens, ck_mask, embed,
                                  out_enc, out_mask);
    tail_kernel<<<PN, 256>>>(know_tokens, ck_mask, cs_ids, use_cs_ids, embed,
                             out_enc, out_mask, out_ck_attn);
}

// round 9
// speedup vs baseline: 1.2700x; 1.0980x over previous
#include <cuda_runtime.h>
#include <cuda_bf16.h>

// Problem constants
#define PN   64
#define PTC  256
#define PK   32
#define PTK  64
#define PD   256
#define D4   (PD/4)          // 64 float4 per row
#define FULL_T (PTK + PTC)   // 320

#define NB_CTX  PN                          // 64 ctx pool+gather blocks (first!)
#define NB_MEGA (NB_CTX + PN * PK)          // 64 + 2048 = 2112

// Scratch (device globals — no allocation allowed)
__device__ float g_ctx_use[PN * PD];
__device__ float g_know_use[PN * PK * PD];

// ck_mask dtype probe: jax bool may arrive as 1-byte bool or int32.
__device__ __forceinline__ bool ck_mask_at(const unsigned char* p, int idx) {
    unsigned int w0 = *(const unsigned int*)p;
    if ((w0 & 0xFFFFFF00u) != 0u) {
        return p[idx] != 0;                          // int8 bool layout
    } else {
        return ((const int*)p)[idx] != 0;            // int32 layout
    }
}

// 8-wide batched accumulate (know path): 8 independent LDG.128.CG, then FMAs.
__device__ __forceinline__ void batch8(const float4* __restrict__ e4,
                                       const int* __restrict__ toks,
                                       int t0, int j,
                                       float4& acc, float& lenf)
{
    int tk[8];
    #pragma unroll
    for (int i = 0; i < 8; i++) tk[i] = toks[t0 + i];
    float4 v[8];
    #pragma unroll
    for (int i = 0; i < 8; i++) v[i] = __ldcg(&e4[(size_t)tk[i] * D4 + j]);
    #pragma unroll
    for (int i = 0; i < 8; i++) {
        float w = (tk[i] != 0) ? 1.0f : 0.0f;
        acc.x = fmaf(w, v[i].x, acc.x);
        acc.y = fmaf(w, v[i].y, acc.y);
        acc.z = fmaf(w, v[i].z, acc.z);
        acc.w = fmaf(w, v[i].w, acc.w);
        lenf += w;
    }
}

// ---------------------------------------------------------------------------
// Mega kernel, two roles:
//   b in [0, 64):      ctx pooling FUSED with ctx-row output gather: every
//                      embed fragment loaded for pooling is also written
//                      (masked) to full_enc — deletes 16.8 MB of re-reads.
//   b in [64, 2112):   know pooling (n = (b-64)/32).
// 256 threads, j = tid & 63 (float4 column), tq = tid >> 6 (token group).
// ---------------------------------------------------------------------------
__global__ __launch_bounds__(256, 4)
void mega_kernel(const int* __restrict__ src_tokens,
                 const int* __restrict__ know_tokens,
                 const unsigned char* __restrict__ ckm,
                 const float* __restrict__ embed,
                 float* __restrict__ out_enc,
                 float* __restrict__ out_mask)
{
    __shared__ int    toks[PTC];
    __shared__ float4 part[4][D4];     // 4 KB
    __shared__ float  lenp[4];

    const int tid = threadIdx.x;
    const int j   = tid & 63;
    const int tq  = tid >> 6;
    const int b   = blockIdx.x;
    const float4* __restrict__ e4 = (const float4*)embed;

    float4 acc = make_float4(0.f, 0.f, 0.f, 0.f);
    float  lenf = 0.f;
    float* dst;

    if (b < NB_CTX) {
        // ---- ctx pooling + fused output gather ----
        const int n = b;
        toks[tid] = src_tokens[n * PTC + tid];
        __syncthreads();

        // full_mask for all 256 ctx rows of this n
        out_mask[(size_t)n * FULL_T + PTK + tid] = (toks[tid] != 0) ? 1.0f : 0.0f;

        float4* __restrict__ oe4 = (float4*)out_enc;
        const int t0 = tq * 64;
        #pragma unroll
        for (int bt = 0; bt < 8; bt++) {
            int tk[8];
            #pragma unroll
            for (int i = 0; i < 8; i++) tk[i] = toks[t0 + bt * 8 + i];
            float4 v[8];
            #pragma unroll
            for (int i = 0; i < 8; i++) v[i] = __ldcg(&e4[(size_t)tk[i] * D4 + j]);
            #pragma unroll
            for (int i = 0; i < 8; i++) {
                const float w = (tk[i] != 0) ? 1.0f : 0.0f;
                acc.x = fmaf(w, v[i].x, acc.x);
                acc.y = fmaf(w, v[i].y, acc.y);
                acc.z = fmaf(w, v[i].z, acc.z);
                acc.w = fmaf(w, v[i].w, acc.w);
                lenf += w;
                const size_t r = (size_t)n * FULL_T + PTK + t0 + bt * 8 + i;
                __stcs(&oe4[r * D4 + j],
                       make_float4(w * v[i].x, w * v[i].y, w * v[i].z, w * v[i].w));
            }
        }
        dst = g_ctx_use + (size_t)n * PD;
    } else {
        // ---- know pooling ----
        const int kb = b - NB_CTX;          // 0 .. 2047
        const int n  = kb / PK;
        if (tid < PTK) toks[tid] = know_tokens[(size_t)kb * PTK + tid];
        __syncthreads();
        const float cmv = ck_mask_at(ckm, kb) ? 1.0f : 0.0f;

        const int t0 = tq * 16;
        batch8(e4, toks, t0,     j, acc, lenf);
        batch8(e4, toks, t0 + 8, j, acc, lenf);

        acc.x *= cmv; acc.y *= cmv; acc.z *= cmv; acc.w *= cmv;
        lenf *= cmv;
        dst = g_know_use + (size_t)kb * PD;
        (void)n;
    }

    part[tq][j] = acc;
    if (j == 0) lenp[tq] = lenf;
    __syncthreads();

    if (tq == 0) {
        float4 p0 = part[0][j], p1 = part[1][j], p2 = part[2][j], p3 = part[3][j];
        float4 a = make_float4(p0.x + p1.x + p2.x + p3.x,
                               p0.y + p1.y + p2.y + p3.y,
                               p0.z + p1.z + p2.z + p3.z,
                               p0.w + p1.w + p2.w + p3.w);
        float L = lenp[0] + lenp[1] + lenp[2] + lenp[3];
        float s = rsqrtf(256.0f * fmaxf(L, 1.0f));
        ((float4*)dst)[j] = make_float4(a.x * s, a.y * s, a.z * s, a.w * s);
    }
}

// ---------------------------------------------------------------------------
// Tail: 4 blocks per n (256 blocks total). Each block redundantly computes
// the 32 scores + argmax (L2-hot, cheap), then gathers its 16 of the 64
// selected knowledge rows. Part 0 also writes ck_attn.
// ---------------------------------------------------------------------------
__global__ __launch_bounds__(256)
void tail_kernel(const int* __restrict__ know_tokens,
                 const unsigned char* __restrict__ ckm,
                 const int* __restrict__ cs_ids,
                 const int* __restrict__ use_cs_ids,
                 const float* __restrict__ embed,
                 float* __restrict__ out_enc,
                 float* __restrict__ out_mask,
                 float* __restrict__ out_ck_attn)
{
    const int n    = blockIdx.x >> 2;
    const int prt  = blockIdx.x & 3;
    const int tid  = threadIdx.x;
    const int wid  = tid >> 5;
    const int lane = tid & 31;
    const int j    = tid & 63;
    const int tq   = tid >> 6;
    __shared__ float scores[PK];
    __shared__ int   toks[16];
    __shared__ int   cs_sh;

    // ---- scores (redundant across the 4 parts; data is L2-hot) ----
    const float* __restrict__ cu = g_ctx_use + (size_t)n * PD;
    float cureg[8];
    #pragma unroll
    for (int c = 0; c < 8; c++) cureg[c] = cu[lane + 32 * c];

    #pragma unroll
    for (int kk = 0; kk < 4; kk++) {
        const int k = wid + kk * 8;
        const float* __restrict__ ku = g_know_use + ((size_t)n * PK + k) * PD;
        float p = 0.f;
        #pragma unroll
        for (int c = 0; c < 8; c++) p = fmaf(ku[lane + 32 * c], cureg[c], p);
        #pragma unroll
        for (int o = 16; o; o >>= 1) p += __shfl_xor_sync(0xFFFFFFFFu, p, o);
        if (lane == 0) scores[k] = p;
    }
    __syncthreads();

    if (tid == 0) {
        int use = *use_cs_ids;
        int best = 0;
        float bv = -__int_as_float(0x7f800000);  // -inf
        #pragma unroll
        for (int k = 0; k < PK; k++) {
            float v = ck_mask_at(ckm, n * PK + k) ? scores[k] : -__int_as_float(0x7f800000);
            if (v > bv) { bv = v; best = k; }   // first-max matches jnp.argmax
        }
        cs_sh = use ? cs_ids[n] : best;
    }
    if (prt == 0 && tid < PK) {
        bool cm = ck_mask_at(ckm, n * PK + tid);
        out_ck_attn[n * PK + tid] = cm ? scores[tid] : 0.0f;
    }
    __syncthreads();

    // ---- gather this part's 16 selected knowledge rows ----
    const int cs = cs_sh;
    const int tbase = prt * 16;
    if (tid < 16) toks[tid] = know_tokens[((size_t)n * PK + cs) * PTK + tbase + tid];
    __syncthreads();
    const bool cmn = ck_mask_at(ckm, n * PK + cs);
    const float4* __restrict__ e4 = (const float4*)embed;

    // 16 rows over 4 tq-groups -> 4 rows/thread, 4-deep batched.
    int   rows[4];
    float ws[4];
    float4 v[4];
    #pragma unroll
    for (int i = 0; i < 4; i++) {
        const int t = tq + 4 * i;              // local row 0..15
        const int tok = toks[t];
        const bool m = cmn && (tok != 0);
        ws[i]   = m ? 1.0f : 0.0f;
        rows[i] = m ? tok : 0;
    }
    #pragma unroll
    for (int i = 0; i < 4; i++) v[i] = __ldcg(&e4[(size_t)rows[i] * D4 + j]);
    #pragma unroll
    for (int i = 0; i < 4; i++) {
        const int t = tq + 4 * i;
        const size_t r = (size_t)n * FULL_T + tbase + t;
        __stcs(&((float4*)out_enc)[r * D4 + j],
               make_float4(ws[i] * v[i].x, ws[i] * v[i].y,
                           ws[i] * v[i].z, ws[i] * v[i].w));
    }
    if (tid < 16) {
        const int tok = toks[tid];
        out_mask[(size_t)n * FULL_T + tbase + tid] = (cmn && tok != 0) ? 1.0f : 0.0f;
    }
}

// ---------------------------------------------------------------------------
extern "C" void kernel_launch(void* const* d_in, const int* in_sizes, int n_in,
                              void* d_out, int out_size)
{
    const int*           src_tokens  = (const int*)d_in[0];            // [N,TC]
    const int*           know_tokens = (const int*)d_in[1];            // [N,K,TK]
    const unsigned char* ck_mask     = (const unsigned char*)d_in[2];  // [N,K] bool
    const int*           cs_ids      = (const int*)d_in[3];            // [N]
    const int*           use_cs_ids  = (const int*)d_in[4];            // scalar
    const float*         embed       = (const float*)d_in[5];          // [V,D]

    float* out = (float*)d_out;
    float* out_enc     = out;                                   // N*320*256
    float* out_mask    = out + (size_t)PN * FULL_T * PD;        // N*320
    float* out_ck_attn = out_mask + (size_t)PN * FULL_T;        // N*K

    mega_kernel<<<NB_MEGA, 256>>>(src_tokens, know_tokens, ck_mask, embed,
                                  out_enc, out_mask);
    tail_kernel<<<PN * 4, 256>>>(know_tokens, ck_mask, cs_ids, use_cs_ids, embed,
                                 out_enc, out_mask, out_ck_attn);
}

// round 10
// speedup vs baseline: 1.4247x; 1.1218x over previous
#include <cuda_runtime.h>
#include <cuda_bf16.h>

// Problem constants
#define PN   64
#define PTC  256
#define PK   32
#define PTK  64
#define PD   256
#define D4   (PD/4)          // 64 float4 per row
#define FULL_T (PTK + PTC)   // 320

#define NB_CTX  PN                          // 64 ctx pool+gather blocks (first!)
#define NB_MEGA (NB_CTX + PN * PK)          // 64 + 2048 = 2112

// Scratch (device globals — no allocation allowed)
__device__ float g_ctx_use[PN * PD];
__device__ float g_know_use[PN * PK * PD];

// ck_mask dtype probe: jax bool may arrive as 1-byte bool or int32.
__device__ __forceinline__ bool ck_mask_at(const unsigned char* p, int idx) {
    unsigned int w0 = *(const unsigned int*)p;
    if ((w0 & 0xFFFFFF00u) != 0u) {
        return p[idx] != 0;                          // int8 bool layout
    } else {
        return ((const int*)p)[idx] != 0;            // int32 layout
    }
}

// 8-wide batched accumulate (know path): 8 independent LDG.128.CG, then FMAs.
__device__ __forceinline__ void batch8(const float4* __restrict__ e4,
                                       const int* __restrict__ toks,
                                       int t0, int j,
                                       float4& acc, float& lenf)
{
    int tk[8];
    #pragma unroll
    for (int i = 0; i < 8; i++) tk[i] = toks[t0 + i];
    float4 v[8];
    #pragma unroll
    for (int i = 0; i < 8; i++) v[i] = __ldcg(&e4[(size_t)tk[i] * D4 + j]);
    #pragma unroll
    for (int i = 0; i < 8; i++) {
        float w = (tk[i] != 0) ? 1.0f : 0.0f;
        acc.x = fmaf(w, v[i].x, acc.x);
        acc.y = fmaf(w, v[i].y, acc.y);
        acc.z = fmaf(w, v[i].z, acc.z);
        acc.w = fmaf(w, v[i].w, acc.w);
        lenf += w;
    }
}

// ---------------------------------------------------------------------------
// Mega kernel, two roles:
//   b in [0, 64):      ctx pooling FUSED with ctx-row output gather.
//   b in [64, 2112):   know pooling (kb = b-64).
// ---------------------------------------------------------------------------
__global__ __launch_bounds__(256, 4)
void mega_kernel(const int* __restrict__ src_tokens,
                 const int* __restrict__ know_tokens,
                 const unsigned char* __restrict__ ckm,
                 const float* __restrict__ embed,
                 float* __restrict__ out_enc,
                 float* __restrict__ out_mask)
{
    __shared__ int    toks[PTC];
    __shared__ float4 part[4][D4];     // 4 KB
    __shared__ float  lenp[4];

    const int tid = threadIdx.x;
    const int j   = tid & 63;
    const int tq  = tid >> 6;
    const int b   = blockIdx.x;
    const float4* __restrict__ e4 = (const float4*)embed;

    float4 acc = make_float4(0.f, 0.f, 0.f, 0.f);
    float  lenf = 0.f;
    float* dst;

    if (b < NB_CTX) {
        // ---- ctx pooling + fused output gather ----
        const int n = b;
        toks[tid] = src_tokens[n * PTC + tid];
        __syncthreads();

        out_mask[(size_t)n * FULL_T + PTK + tid] = (toks[tid] != 0) ? 1.0f : 0.0f;

        float4* __restrict__ oe4 = (float4*)out_enc;
        const int t0 = tq * 64;
        #pragma unroll
        for (int bt = 0; bt < 8; bt++) {
            int tk[8];
            #pragma unroll
            for (int i = 0; i < 8; i++) tk[i] = toks[t0 + bt * 8 + i];
            float4 v[8];
            #pragma unroll
            for (int i = 0; i < 8; i++) v[i] = __ldcg(&e4[(size_t)tk[i] * D4 + j]);
            #pragma unroll
            for (int i = 0; i < 8; i++) {
                const float w = (tk[i] != 0) ? 1.0f : 0.0f;
                acc.x = fmaf(w, v[i].x, acc.x);
                acc.y = fmaf(w, v[i].y, acc.y);
                acc.z = fmaf(w, v[i].z, acc.z);
                acc.w = fmaf(w, v[i].w, acc.w);
                lenf += w;
                const size_t r = (size_t)n * FULL_T + PTK + t0 + bt * 8 + i;
                __stcs(&oe4[r * D4 + j],
                       make_float4(w * v[i].x, w * v[i].y, w * v[i].z, w * v[i].w));
            }
        }
        dst = g_ctx_use + (size_t)n * PD;
    } else {
        // ---- know pooling ----
        const int kb = b - NB_CTX;          // 0 .. 2047
        if (tid < PTK) toks[tid] = know_tokens[(size_t)kb * PTK + tid];
        __syncthreads();
        const float cmv = ck_mask_at(ckm, kb) ? 1.0f : 0.0f;

        const int t0 = tq * 16;
        batch8(e4, toks, t0,     j, acc, lenf);
        batch8(e4, toks, t0 + 8, j, acc, lenf);

        acc.x *= cmv; acc.y *= cmv; acc.z *= cmv; acc.w *= cmv;
        lenf *= cmv;
        dst = g_know_use + (size_t)kb * PD;
    }

    part[tq][j] = acc;
    if (j == 0) lenp[tq] = lenf;
    __syncthreads();

    if (tq == 0) {
        float4 p0 = part[0][j], p1 = part[1][j], p2 = part[2][j], p3 = part[3][j];
        float4 a = make_float4(p0.x + p1.x + p2.x + p3.x,
                               p0.y + p1.y + p2.y + p3.y,
                               p0.z + p1.z + p2.z + p3.z,
                               p0.w + p1.w + p2.w + p3.w);
        float L = lenp[0] + lenp[1] + lenp[2] + lenp[3];
        float s = rsqrtf(256.0f * fmaxf(L, 1.0f));
        ((float4*)dst)[j] = make_float4(a.x * s, a.y * s, a.z * s, a.w * s);
    }
}

// ---------------------------------------------------------------------------
// Tail: 4 blocks per n (256 blocks). PDL: blocks launch while mega drains,
// then wait at cudaGridDependencySynchronize() before touching its outputs.
// Each block redundantly computes the 32 scores + argmax (L2-hot), then
// gathers its 16 of the 64 selected knowledge rows. Part 0 writes ck_attn.
// ---------------------------------------------------------------------------
__global__ __launch_bounds__(256)
void tail_kernel(const int* __restrict__ know_tokens,
                 const unsigned char* __restrict__ ckm,
                 const int* __restrict__ cs_ids,
                 const int* __restrict__ use_cs_ids,
                 const float* __restrict__ embed,
                 float* __restrict__ out_enc,
                 float* __restrict__ out_mask,
                 float* __restrict__ out_ck_attn)
{
    const int n    = blockIdx.x >> 2;
    const int prt  = blockIdx.x & 3;
    const int tid  = threadIdx.x;
    const int wid  = tid >> 5;
    const int lane = tid & 31;
    const int j    = tid & 63;
    const int tq   = tid >> 6;
    __shared__ float scores[PK];
    __shared__ int   toks[16];
    __shared__ int   cs_sh;

    // Prolog on input-only data (safe before the dependency sync).
    const int use = *use_cs_ids;
    const int cs_id_n = cs_ids[n];

    // Wait for mega's g_ctx_use / g_know_use to be published.
    cudaGridDependencySynchronize();

    // ---- scores (redundant across the 4 parts; data is L2-hot) ----
    const float* __restrict__ cu = g_ctx_use + (size_t)n * PD;
    float cureg[8];
    #pragma unroll
    for (int c = 0; c < 8; c++) cureg[c] = cu[lane + 32 * c];

    #pragma unroll
    for (int kk = 0; kk < 4; kk++) {
        const int k = wid + kk * 8;
        const float* __restrict__ ku = g_know_use + ((size_t)n * PK + k) * PD;
        float p = 0.f;
        #pragma unroll
        for (int c = 0; c < 8; c++) p = fmaf(ku[lane + 32 * c], cureg[c], p);
        #pragma unroll
        for (int o = 16; o; o >>= 1) p += __shfl_xor_sync(0xFFFFFFFFu, p, o);
        if (lane == 0) scores[k] = p;
    }
    __syncthreads();

    if (tid == 0) {
        int best = 0;
        float bv = -__int_as_float(0x7f800000);  // -inf
        #pragma unroll
        for (int k = 0; k < PK; k++) {
            float v = ck_mask_at(ckm, n * PK + k) ? scores[k] : -__int_as_float(0x7f800000);
            if (v > bv) { bv = v; best = k; }   // first-max matches jnp.argmax
        }
        cs_sh = use ? cs_id_n : best;
    }
    if (prt == 0 && tid < PK) {
        bool cm = ck_mask_at(ckm, n * PK + tid);
        out_ck_attn[n * PK + tid] = cm ? scores[tid] : 0.0f;
    }
    __syncthreads();

    // ---- gather this part's 16 selected knowledge rows ----
    const int cs = cs_sh;
    const int tbase = prt * 16;
    if (tid < 16) toks[tid] = know_tokens[((size_t)n * PK + cs) * PTK + tbase + tid];
    __syncthreads();
    const bool cmn = ck_mask_at(ckm, n * PK + cs);
    const float4* __restrict__ e4 = (const float4*)embed;

    int   rows[4];
    float ws[4];
    float4 v[4];
    #pragma unroll
    for (int i = 0; i < 4; i++) {
        const int t = tq + 4 * i;              // local row 0..15
        const int tok = toks[t];
        const bool m = cmn && (tok != 0);
        ws[i]   = m ? 1.0f : 0.0f;
        rows[i] = m ? tok : 0;
    }
    #pragma unroll
    for (int i = 0; i < 4; i++) v[i] = __ldcg(&e4[(size_t)rows[i] * D4 + j]);
    #pragma unroll
    for (int i = 0; i < 4; i++) {
        const int t = tq + 4 * i;
        const size_t r = (size_t)n * FULL_T + tbase + t;
        __stcs(&((float4*)out_enc)[r * D4 + j],
               make_float4(ws[i] * v[i].x, ws[i] * v[i].y,
                           ws[i] * v[i].z, ws[i] * v[i].w));
    }
    if (tid < 16) {
        const int tok = toks[tid];
        out_mask[(size_t)n * FULL_T + tbase + tid] = (cmn && tok != 0) ? 1.0f : 0.0f;
    }
}

// ---------------------------------------------------------------------------
extern "C" void kernel_launch(void* const* d_in, const int* in_sizes, int n_in,
                              void* d_out, int out_size)
{
    const int*           src_tokens  = (const int*)d_in[0];            // [N,TC]
    const int*           know_tokens = (const int*)d_in[1];            // [N,K,TK]
    const unsigned char* ck_mask     = (const unsigned char*)d_in[2];  // [N,K] bool
    const int*           cs_ids      = (const int*)d_in[3];            // [N]
    const int*           use_cs_ids  = (const int*)d_in[4];            // scalar
    const float*         embed       = (const float*)d_in[5];          // [V,D]

    float* out = (float*)d_out;
    float* out_enc     = out;                                   // N*320*256
    float* out_mask    = out + (size_t)PN * FULL_T * PD;        // N*320
    float* out_ck_attn = out_mask + (size_t)PN * FULL_T;        // N*K

    mega_kernel<<<NB_MEGA, 256>>>(src_tokens, know_tokens, ck_mask, embed,
                                  out_enc, out_mask);

    // Tail via PDL: launches while mega drains; waits inside the kernel.
    cudaLaunchAttribute attrs[1];
    attrs[0].id = cudaLaunchAttributeProgrammaticStreamSerialization;
    attrs[0].val.programmaticStreamSerializationAllowed = 1;

    cudaLaunchConfig_t cfg = {};
    cfg.gridDim  = dim3(PN * 4, 1, 1);
    cfg.blockDim = dim3(256, 1, 1);
    cfg.dynamicSmemBytes = 0;
    cfg.stream = 0;                    // legacy default stream (capture target)
    cfg.attrs = attrs;
    cfg.numAttrs = 1;

    cudaError_t err = cudaLaunchKernelEx(&cfg, tail_kernel,
                                         know_tokens, ck_mask, cs_ids, use_cs_ids,
                                         embed, out_enc, out_mask, out_ck_attn);
    if (err != cudaSuccess) {
        // Fallback: plain launch (cudaGridDependencySynchronize is a no-op
        // when there is no programmatic dependency).
        tail_kernel<<<PN * 4, 256>>>(know_tokens, ck_mask, cs_ids, use_cs_ids,
                                     embed, out_enc, out_mask, out_ck_attn);
    }
}